// round 14
// baseline (speedup 1.0000x reference)
#include <cuda_runtime.h>
#include <cuda_fp16.h>
#include <cstdint>

// Problem constants
#define Bc   32
#define Tc   512
#define Hc   256
#define Lc   2048
#define NLc  4

static const int ROWS_DUR = Bc * Tc;   // 16384
static const int ROWS_MEL = Bc * Lc;   // 65536
static const int N_PIT_TILES = ROWS_MEL / 64;   // 1024
static const int N_DUR_TILES = ROWS_DUR / 64;   // 256

// Scratch (device globals; no runtime allocation)
__device__ int            g_idx[Bc * Lc];
__device__ unsigned char  g_mmask[Bc * Lc];     // 1 = padded frame
// Fragment-order weight blob (single fp16), uint4 layout:
// [pred(3)][layer(4)][kstep(16)][npair(16)][lane(32)] x uint4
// uint4 = { frag(2*npair):(b0,b1), frag(2*npair+1):(b0,b1) } fp16x2 each
__device__ __align__(128) uint4 g_wblob[3 * 4 * 16 * 16 * 32];

__device__ __forceinline__ uint32_t smem_u32(const void* p) {
    uint32_t a;
    asm("{ .reg .u64 t; cvta.to.shared.u64 t, %1; cvt.u32.u64 %0, t; }" : "=r"(a) : "l"(p));
    return a;
}
__device__ __forceinline__ uint32_t pack_h2(float a, float b) {
    __half2 t = __floats2half2_rn(a, b);
    return *reinterpret_cast<uint32_t*>(&t);
}
__device__ __forceinline__ void mma16816(float* c, const uint32_t* a, uint32_t b0, uint32_t b1) {
    asm volatile(
        "mma.sync.aligned.m16n8k16.row.col.f32.f16.f16.f32 "
        "{%0,%1,%2,%3}, {%4,%5,%6,%7}, {%8,%9}, {%0,%1,%2,%3};"
        : "+f"(c[0]), "+f"(c[1]), "+f"(c[2]), "+f"(c[3])
        : "r"(a[0]), "r"(a[1]), "r"(a[2]), "r"(a[3]), "r"(b0), "r"(b1));
}
__device__ __forceinline__ void ldmatrix_x4(uint32_t* r, uint32_t smem_addr) {
    asm volatile("ldmatrix.sync.aligned.m8n8.x4.shared.b16 {%0,%1,%2,%3}, [%4];"
        : "=r"(r[0]), "=r"(r[1]), "=r"(r[2]), "=r"(r[3]) : "r"(smem_addr));
}

// ============================================================
// Fused prep (blocks 0..383) + length regulator (blocks 384..415).
// prep: fp32 W[k][n] -> single fp16 mma fragments (uint4 pairs).
// regulate: cumsum + searchsorted + masks (1 block / batch).
// ============================================================
__global__ void __launch_bounds__(512)
prep_regulate_kernel(const float* __restrict__ durW,
                     const float* __restrict__ pitW,
                     const float* __restrict__ enW,
                     const int* __restrict__ dur,
                     float* __restrict__ out_mellen,
                     float* __restrict__ out_melmask)
{
    if (blockIdx.x < 384) {
        int i = blockIdx.x * 512 + threadIdx.x;   // 196608 total
        int lane  = i & 31;
        int nsub  = (i >> 5) & 31;
        int kstep = (i >> 10) & 15;
        int l     = (i >> 14) & 3;
        int p     = i >> 16;                      // 0..2
        const float* W = (p == 0 ? durW : (p == 1 ? pitW : enW)) + l * Hc * Hc;
        int n  = nsub * 8 + (lane >> 2);
        int tg = lane & 3;
        int kA = kstep * 16 + tg * 2;
        int kB = kA + 8;
        uint2 v;
        v.x = pack_h2(W[kA * Hc + n], W[(kA + 1) * Hc + n]);
        v.y = pack_h2(W[kB * Hc + n], W[(kB + 1) * Hc + n]);
        size_t pos4 = ((((size_t)(p * 4 + l) * 16 + kstep) * 16 + (nsub >> 1)) * 32 + lane);
        ((uint2*)g_wblob)[pos4 * 2 + (nsub & 1)] = v;
    } else {
        __shared__ int cum[Tc];
        const int b = blockIdx.x - 384;
        const int t = threadIdx.x;
        cum[t] = dur[b * Tc + t];
        __syncthreads();
        for (int off = 1; off < Tc; off <<= 1) {
            int v = (t >= off) ? cum[t - off] : 0;
            __syncthreads();
            cum[t] += v;
            __syncthreads();
        }
        const int mel_len = min(cum[Tc - 1], Lc);
        for (int m = t; m < Lc; m += Tc) {
            int lo = 0, hi = Tc;
            while (lo < hi) {
                int mid = (lo + hi) >> 1;
                if (cum[mid] <= m) lo = mid + 1; else hi = mid;
            }
            int idx = min(lo, Tc - 1);
            bool pad = (m >= mel_len);
            g_idx[b * Lc + m]       = idx;
            g_mmask[b * Lc + m]     = pad ? 1 : 0;
            out_melmask[b * Lc + m] = pad ? 1.0f : 0.0f;
        }
        if (t == 0) out_mellen[b] = (float)mel_len;
    }
}

// ============================================================
// mma.sync predictor. 256 threads = 8 warps (2M x 4N), tile 64x256.
// 2 CTAs/SM. A fp16 in SMEM (ldmatrix per kstep). B direct from L2
// via LDG.128, ping-pong registers, one kstep ahead; the NEXT layer's
// kstep-0 B is prefetched across the epilogue/barrier boundary.
// pitch CTAs also write o_main in the tail.
// ============================================================
#define PITCH 264
#define OFF_HHI   0
#define OFF_BIAS  (64 * PITCH * 2)                  // 33792
#define OFF_WHEAD (OFF_BIAS + 4 * 256 * 4)          // 37888
#define OFF_HEAD  (OFF_WHEAD + 256 * 4)             // 38912
#define SMEM_TOTAL (OFF_HEAD + 64 * 4)              // 39168

__global__ void __launch_bounds__(256, 2)
predictor_mma(const float* __restrict__ x,
              const float* __restrict__ src_seq,
              const unsigned char* __restrict__ src_mask,
              const float* __restrict__ dur_b, const float* __restrict__ pit_b,
              const float* __restrict__ en_b,
              const float* __restrict__ dur_w, const float* __restrict__ pit_w,
              const float* __restrict__ en_w,
              const float* __restrict__ dur_b2, const float* __restrict__ pit_b2,
              const float* __restrict__ en_b2,
              const float* __restrict__ pitch_t, const float* __restrict__ energy_t,
              const float* __restrict__ pemb, const float* __restrict__ eemb,
              float* __restrict__ o_logdur, float* __restrict__ o_pitch,
              float* __restrict__ o_energy, float* __restrict__ o_main)
{
    extern __shared__ char smem[];
    __half* h_hi = (__half*)(smem + OFF_HHI);
    float*  bias_s  = (float*)(smem + OFF_BIAS);
    float*  whead_s = (float*)(smem + OFF_WHEAD);
    float*  headsum = (float*)(smem + OFF_HEAD);

    const int tid  = threadIdx.x;
    const int lane = tid & 31;
    const int wid  = tid >> 5;
    const int warpM = wid >> 2;          // 0..1 (32 rows each)
    const int warpN = wid & 3;           // 0..3 (64 cols each)
    const int g  = lane >> 2;
    const int tg = lane & 3;
    const int bid = blockIdx.x;

    int pred;
    long r0;
    const float* bias;
    const float* wh;
    const float* b2;
    float* out;
    if (bid < N_PIT_TILES) {
        pred = 1; r0 = (long)bid * 64;
        bias = pit_b; wh = pit_w; b2 = pit_b2; out = o_pitch;
    } else if (bid < 2 * N_PIT_TILES) {
        pred = 2; r0 = (long)(bid - N_PIT_TILES) * 64;
        bias = en_b; wh = en_w; b2 = en_b2; out = o_energy;
    } else {
        pred = 0; r0 = (long)(bid - 2 * N_PIT_TILES) * 64;
        bias = dur_b; wh = dur_w; b2 = dur_b2; out = o_logdur;
    }
    // B uint4 base for this pred/warpN/lane
    const uint4* Bbase = g_wblob + ((size_t)pred * 4 * 16 * 16 + warpN * 4) * 32 + lane;

    // prefetch layer 0 / kstep 0 B fragments FIRST (overlaps prologue)
    uint4 B0[4], B1[4];
    #pragma unroll
    for (int jj = 0; jj < 4; jj++) B0[jj] = __ldg(Bbase + jj * 32);

    // bias + head weights + headsum init
    for (int i = tid; i < NLc * Hc; i += 256) bias_s[i] = bias[i];
    whead_s[tid] = wh[tid];
    if (tid < 64) headsum[tid] = 0.f;

    // A init: fp32 input -> fp16 in SMEM (gather for pitch/energy)
    {
        const int row = tid >> 2;
        const int c0  = (tid & 3) * 64;
        const long r  = r0 + row;
        const float* xr;
        bool zero = false;
        if (pred == 0) {
            xr = x + r * (long)Hc + c0;
        } else {
            const long b = r / Lc;
            xr = x + ((long)b * Tc + g_idx[r]) * (long)Hc + c0;
            zero = (g_mmask[r] != 0);
        }
        __half* dh = h_hi + row * PITCH + c0;
        #pragma unroll
        for (int q = 0; q < 16; q++) {
            float4 v = ((const float4*)xr)[q];
            if (zero) v = make_float4(0.f, 0.f, 0.f, 0.f);
            *(uint32_t*)(dh + q * 4)     = pack_h2(v.x, v.y);
            *(uint32_t*)(dh + q * 4 + 2) = pack_h2(v.z, v.w);
        }
    }

    // per-warp ldmatrix base addresses (bytes), one per m-subtile
    const uint32_t hbase = smem_u32(h_hi);
    uint32_t a_addr[2];
    #pragma unroll
    for (int m = 0; m < 2; m++) {
        const int rr = warpM * 32 + m * 16 + (lane & 15);
        a_addr[m] = hbase + (uint32_t)(rr * PITCH + (lane >> 4) * 8) * 2;
    }

    float acc[2][8][4];
    #pragma unroll
    for (int m = 0; m < 2; m++)
        #pragma unroll
        for (int j = 0; j < 8; j++)
            #pragma unroll
            for (int q = 0; q < 4; q++) acc[m][j][q] = 0.f;

    float hp[4] = {0.f, 0.f, 0.f, 0.f};   // head partials

    #pragma unroll 1
    for (int l = 0; l < NLc; l++) {
        __syncthreads();   // A of this layer visible to all warps

        const uint4* Bl = Bbase + (size_t)l * 16 * 16 * 32;   // layer base

        // 2x-unrolled kstep loop: even kstep uses B0 (prefetches B1),
        // odd kstep uses B1 (prefetches B0). At the last odd kstep,
        // prefetch the NEXT layer's kstep-0 chunk into B0 so its L2
        // latency overlaps the epilogue + barrier.
        #pragma unroll 1
        for (int ks2 = 0; ks2 < 8; ks2++) {
            {   // even kstep: 2*ks2
                const int ks = 2 * ks2;
                uint32_t a[2][4];
                ldmatrix_x4(a[0], a_addr[0] + ks * 32);
                ldmatrix_x4(a[1], a_addr[1] + ks * 32);
                const uint4* Bk = Bl + (size_t)(ks + 1) * 16 * 32;
                #pragma unroll
                for (int jj = 0; jj < 4; jj++) B1[jj] = __ldg(Bk + jj * 32);
                #pragma unroll
                for (int jj = 0; jj < 4; jj++) {
                    mma16816(acc[0][2 * jj],     a[0], B0[jj].x, B0[jj].y);
                    mma16816(acc[1][2 * jj],     a[1], B0[jj].x, B0[jj].y);
                    mma16816(acc[0][2 * jj + 1], a[0], B0[jj].z, B0[jj].w);
                    mma16816(acc[1][2 * jj + 1], a[1], B0[jj].z, B0[jj].w);
                }
            }
            {   // odd kstep: 2*ks2+1
                const int ks = 2 * ks2 + 1;
                uint32_t a[2][4];
                ldmatrix_x4(a[0], a_addr[0] + ks * 32);
                ldmatrix_x4(a[1], a_addr[1] + ks * 32);
                if (ks2 < 7) {
                    const uint4* Bk = Bl + (size_t)(ks + 1) * 16 * 32;
                    #pragma unroll
                    for (int jj = 0; jj < 4; jj++) B0[jj] = __ldg(Bk + jj * 32);
                } else if (l + 1 < NLc) {
                    // next layer, kstep 0
                    const uint4* Bk = Bl + (size_t)16 * 16 * 32;
                    #pragma unroll
                    for (int jj = 0; jj < 4; jj++) B0[jj] = __ldg(Bk + jj * 32);
                }
                #pragma unroll
                for (int jj = 0; jj < 4; jj++) {
                    mma16816(acc[0][2 * jj],     a[0], B1[jj].x, B1[jj].y);
                    mma16816(acc[1][2 * jj],     a[1], B1[jj].x, B1[jj].y);
                    mma16816(acc[0][2 * jj + 1], a[0], B1[jj].z, B1[jj].w);
                    mma16816(acc[1][2 * jj + 1], a[1], B1[jj].z, B1[jj].w);
                }
            }
        }

        // ---- layer epilogue ----
        const float* bl = bias_s + l * Hc;
        if (l < NLc - 1) {
            __syncthreads();   // all warps done reading A of this layer
            #pragma unroll
            for (int m = 0; m < 2; m++) {
                const int rr = warpM * 32 + m * 16 + g;
                #pragma unroll
                for (int j = 0; j < 8; j++) {
                    const int col = warpN * 64 + j * 8 + tg * 2;
                    float v0 = fmaxf(acc[m][j][0] + bl[col],     0.f);
                    float v1 = fmaxf(acc[m][j][1] + bl[col + 1], 0.f);
                    float v2 = fmaxf(acc[m][j][2] + bl[col],     0.f);
                    float v3 = fmaxf(acc[m][j][3] + bl[col + 1], 0.f);
                    *(uint32_t*)(h_hi + rr * PITCH + col)       = pack_h2(v0, v1);
                    *(uint32_t*)(h_hi + (rr + 8) * PITCH + col) = pack_h2(v2, v3);
                    acc[m][j][0] = 0.f; acc[m][j][1] = 0.f;
                    acc[m][j][2] = 0.f; acc[m][j][3] = 0.f;
                }
            }
        } else {
            #pragma unroll
            for (int m = 0; m < 2; m++) {
                #pragma unroll
                for (int j = 0; j < 8; j++) {
                    const int col = warpN * 64 + j * 8 + tg * 2;
                    float w0 = whead_s[col], w1 = whead_s[col + 1];
                    hp[m * 2]     += fmaxf(acc[m][j][0] + bl[col],     0.f) * w0
                                   + fmaxf(acc[m][j][1] + bl[col + 1], 0.f) * w1;
                    hp[m * 2 + 1] += fmaxf(acc[m][j][2] + bl[col],     0.f) * w0
                                   + fmaxf(acc[m][j][3] + bl[col + 1], 0.f) * w1;
                }
            }
        }
    }

    // head reduction: atomicAdd into per-row shared slots
    #pragma unroll
    for (int m = 0; m < 2; m++) {
        const int rr = warpM * 32 + m * 16 + g;
        atomicAdd(&headsum[rr],     hp[m * 2]);
        atomicAdd(&headsum[rr + 8], hp[m * 2 + 1]);
    }
    __syncthreads();

    if (tid < 64) {
        const long r = r0 + tid;
        float val = headsum[tid] + b2[0];
        const bool msk = (pred == 0) ? (src_mask[r] != 0) : (g_mmask[r] != 0);
        if (msk) val = 0.f;
        float res;
        if (pred == 0)      res = (tanhf(val) + 1.f) * src_seq[r * 3 + 2];
        else if (pred == 1) res = fmaxf(val, 0.f);
        else                res = val;
        out[r] = res;
    }

    // pitch CTAs also produce o_main = gather(x) + pemb + eemb for their rows
    if (pred == 1) {
        const int row = tid >> 2;
        const int c0  = (tid & 3) * 64;
        const long r  = r0 + row;
        const long b  = r / Lc;
        const float* xr = x + ((long)b * Tc + g_idx[r]) * (long)Hc + c0;
        const bool zero = (g_mmask[r] != 0);
        const int pi = (int)ceilf(pitch_t[r] * 256.0f);
        const int ei = (int)ceilf(energy_t[r] * 256.0f);
        const float4* pe = (const float4*)(pemb + (size_t)pi * Hc + c0);
        const float4* ee = (const float4*)(eemb + (size_t)ei * Hc + c0);
        float4* dst = (float4*)(o_main + r * (long)Hc + c0);
        #pragma unroll
        for (int q = 0; q < 16; q++) {
            float4 a = ((const float4*)xr)[q];
            if (zero) a = make_float4(0.f, 0.f, 0.f, 0.f);
            float4 p = pe[q], e = ee[q];
            float4 tmp;
            tmp.x = a.x + p.x + e.x;
            tmp.y = a.y + p.y + e.y;
            tmp.z = a.z + p.z + e.z;
            tmp.w = a.w + p.w + e.w;
            dst[q] = tmp;
        }
    }
}

// ============================================================
extern "C" void kernel_launch(void* const* d_in, const int* in_sizes, int n_in,
                              void* d_out, int out_size)
{
    const float* x        = (const float*)d_in[0];   // [B,T,H]
    const float* src_seq  = (const float*)d_in[1];   // [B,T,3]
    const int*   dur_t    = (const int*)  d_in[2];   // [B,T]
    const float* pitch_t  = (const float*)d_in[3];   // [B,L]
    const float* energy_t = (const float*)d_in[4];   // [B,L]
    const unsigned char* src_mask = (const unsigned char*)d_in[5]; // [B,T] bool

    const int base = n_in - 14;
    const float* dur_W  = (const float*)d_in[base + 0];
    const float* dur_b  = (const float*)d_in[base + 1];
    const float* dur_w  = (const float*)d_in[base + 2];
    const float* dur_b2 = (const float*)d_in[base + 3];
    const float* pit_W  = (const float*)d_in[base + 4];
    const float* pit_b  = (const float*)d_in[base + 5];
    const float* pit_w  = (const float*)d_in[base + 6];
    const float* pit_b2 = (const float*)d_in[base + 7];
    const float* en_W   = (const float*)d_in[base + 8];
    const float* en_b   = (const float*)d_in[base + 9];
    const float* en_w   = (const float*)d_in[base + 10];
    const float* en_b2  = (const float*)d_in[base + 11];
    const float* pemb   = (const float*)d_in[base + 12];
    const float* eemb   = (const float*)d_in[base + 13];

    float* out       = (float*)d_out;
    float* o_main    = out;                               // B*L*H
    float* o_logdur  = o_main + (size_t)ROWS_MEL * Hc;    // B*T
    float* o_pitch   = o_logdur + ROWS_DUR;               // B*L
    float* o_energy  = o_pitch + ROWS_MEL;                // B*L
    float* o_mellen  = o_energy + ROWS_MEL;               // B
    float* o_mmask   = o_mellen + Bc;                     // B*L

    cudaFuncSetAttribute(predictor_mma, cudaFuncAttributeMaxDynamicSharedMemorySize, SMEM_TOTAL);

    // 0) fused weight prep + length-regulator metadata
    prep_regulate_kernel<<<384 + Bc, 512>>>(dur_W, pit_W, en_W,
                                            dur_t, o_mellen, o_mmask);

    // 1) predictors + main output in one kernel
    predictor_mma<<<2 * N_PIT_TILES + N_DUR_TILES, 256, SMEM_TOTAL>>>(
        x, src_seq, src_mask,
        dur_b, pit_b, en_b, dur_w, pit_w, en_w, dur_b2, pit_b2, en_b2,
        pitch_t, energy_t, pemb, eemb,
        o_logdur, o_pitch, o_energy, o_main);
}

// round 15
// speedup vs baseline: 1.0223x; 1.0223x over previous
#include <cuda_runtime.h>
#include <cuda_fp16.h>
#include <cstdint>

// Problem constants
#define Bc   32
#define Tc   512
#define Hc   256
#define Lc   2048
#define NLc  4

static const int ROWS_DUR = Bc * Tc;   // 16384
static const int ROWS_MEL = Bc * Lc;   // 65536
static const int N_PIT_TILES = ROWS_MEL / 64;   // 1024
static const int N_DUR_TILES = ROWS_DUR / 64;   // 256

// Scratch (device globals; no runtime allocation)
__device__ int            g_idx[Bc * Lc];
__device__ unsigned char  g_mmask[Bc * Lc];     // 1 = padded frame
// Fragment-order weight blob (single fp16), uint4 layout:
// [pred(3)][layer(4)][kstep(16)][npair(16)][lane(32)] x uint4
__device__ __align__(128) uint4 g_wblob[3 * 4 * 16 * 16 * 32];

__device__ __forceinline__ uint32_t smem_u32(const void* p) {
    uint32_t a;
    asm("{ .reg .u64 t; cvta.to.shared.u64 t, %1; cvt.u32.u64 %0, t; }" : "=r"(a) : "l"(p));
    return a;
}
__device__ __forceinline__ uint32_t pack_h2(float a, float b) {
    __half2 t = __floats2half2_rn(a, b);
    return *reinterpret_cast<uint32_t*>(&t);
}
__device__ __forceinline__ void mma16816(float* c, const uint32_t* a, uint32_t b0, uint32_t b1) {
    asm volatile(
        "mma.sync.aligned.m16n8k16.row.col.f32.f16.f16.f32 "
        "{%0,%1,%2,%3}, {%4,%5,%6,%7}, {%8,%9}, {%0,%1,%2,%3};"
        : "+f"(c[0]), "+f"(c[1]), "+f"(c[2]), "+f"(c[3])
        : "r"(a[0]), "r"(a[1]), "r"(a[2]), "r"(a[3]), "r"(b0), "r"(b1));
}
__device__ __forceinline__ void ldmatrix_x4(uint32_t* r, uint32_t smem_addr) {
    asm volatile("ldmatrix.sync.aligned.m8n8.x4.shared.b16 {%0,%1,%2,%3}, [%4];"
        : "=r"(r[0]), "=r"(r[1]), "=r"(r[2]), "=r"(r[3]) : "r"(smem_addr));
}
// named barrier over 128 threads (ids 1,2; id 0 reserved for full syncs)
__device__ __forceinline__ void half_bar(int id) {
    asm volatile("bar.sync %0, 128;" :: "r"(id) : "memory");
}

// ============================================================
// Weight prep: fp32 W[k][n] -> single fp16 mma fragments (uint4 pairs).
// ============================================================
__global__ void prep_kernel(const float* __restrict__ durW,
                            const float* __restrict__ pitW,
                            const float* __restrict__ enW)
{
    int i = blockIdx.x * 256 + threadIdx.x;   // 196608 total
    int lane  = i & 31;
    int nsub  = (i >> 5) & 31;
    int kstep = (i >> 10) & 15;
    int l     = (i >> 14) & 3;
    int p     = i >> 16;                      // 0..2
    const float* W = (p == 0 ? durW : (p == 1 ? pitW : enW)) + l * Hc * Hc;
    int n  = nsub * 8 + (lane >> 2);
    int tg = lane & 3;
    int kA = kstep * 16 + tg * 2;
    int kB = kA + 8;
    uint2 v;
    v.x = pack_h2(W[kA * Hc + n], W[(kA + 1) * Hc + n]);
    v.y = pack_h2(W[kB * Hc + n], W[(kB + 1) * Hc + n]);
    size_t pos4 = ((((size_t)(p * 4 + l) * 16 + kstep) * 16 + (nsub >> 1)) * 32 + lane);
    ((uint2*)g_wblob)[pos4 * 2 + (nsub & 1)] = v;
}

// ============================================================
// Length regulator: cumsum + searchsorted + masks (1 block / batch)
// ============================================================
__global__ void regulate_kernel(const int* __restrict__ dur,
                                float* __restrict__ out_mellen,
                                float* __restrict__ out_melmask)
{
    __shared__ int cum[Tc];
    const int b = blockIdx.x;
    const int t = threadIdx.x;
    cum[t] = dur[b * Tc + t];
    __syncthreads();
    for (int off = 1; off < Tc; off <<= 1) {
        int v = (t >= off) ? cum[t - off] : 0;
        __syncthreads();
        cum[t] += v;
        __syncthreads();
    }
    const int mel_len = min(cum[Tc - 1], Lc);
    for (int m = t; m < Lc; m += Tc) {
        int lo = 0, hi = Tc;
        while (lo < hi) {
            int mid = (lo + hi) >> 1;
            if (cum[mid] <= m) lo = mid + 1; else hi = mid;
        }
        int idx = min(lo, Tc - 1);
        bool pad = (m >= mel_len);
        g_idx[b * Lc + m]       = idx;
        g_mmask[b * Lc + m]     = pad ? 1 : 0;
        out_melmask[b * Lc + m] = pad ? 1.0f : 0.0f;
    }
    if (t == 0) out_mellen[b] = (float)mel_len;
}

// ============================================================
// mma.sync predictor. 256 threads = 8 warps (2M x 4N), tile 64x256.
// 2 CTAs/SM. The two warpM halves (tids 0-127 / 128-255) own disjoint
// row ranges and run INDEPENDENTLY through all 4 layers using named
// barriers (128-thread scope) — one half's epilogue overlaps the
// other's MMA mainloop. B direct from L2 via LDG.128 ping-pong.
// ============================================================
#define PITCH 264
#define OFF_HHI   0
#define OFF_BIAS  (64 * PITCH * 2)                  // 33792
#define OFF_WHEAD (OFF_BIAS + 4 * 256 * 4)          // 37888
#define OFF_HEAD  (OFF_WHEAD + 256 * 4)             // 38912
#define SMEM_TOTAL (OFF_HEAD + 64 * 4)              // 39168

__global__ void __launch_bounds__(256, 2)
predictor_mma(const float* __restrict__ x,
              const float* __restrict__ src_seq,
              const unsigned char* __restrict__ src_mask,
              const float* __restrict__ dur_b, const float* __restrict__ pit_b,
              const float* __restrict__ en_b,
              const float* __restrict__ dur_w, const float* __restrict__ pit_w,
              const float* __restrict__ en_w,
              const float* __restrict__ dur_b2, const float* __restrict__ pit_b2,
              const float* __restrict__ en_b2,
              const float* __restrict__ pitch_t, const float* __restrict__ energy_t,
              const float* __restrict__ pemb, const float* __restrict__ eemb,
              float* __restrict__ o_logdur, float* __restrict__ o_pitch,
              float* __restrict__ o_energy, float* __restrict__ o_main)
{
    extern __shared__ char smem[];
    __half* h_hi = (__half*)(smem + OFF_HHI);
    float*  bias_s  = (float*)(smem + OFF_BIAS);
    float*  whead_s = (float*)(smem + OFF_WHEAD);
    float*  headsum = (float*)(smem + OFF_HEAD);

    const int tid  = threadIdx.x;
    const int lane = tid & 31;
    const int wid  = tid >> 5;
    const int warpM = wid >> 2;          // 0..1 -> half id (tids 0-127 / 128-255)
    const int warpN = wid & 3;           // 0..3 (64 cols each)
    const int g  = lane >> 2;
    const int tg = lane & 3;
    const int bid = blockIdx.x;
    const int barid = 1 + warpM;         // named barrier per half

    int pred;
    long r0;
    const float* bias;
    const float* wh;
    const float* b2;
    float* out;
    if (bid < N_PIT_TILES) {
        pred = 1; r0 = (long)bid * 64;
        bias = pit_b; wh = pit_w; b2 = pit_b2; out = o_pitch;
    } else if (bid < 2 * N_PIT_TILES) {
        pred = 2; r0 = (long)(bid - N_PIT_TILES) * 64;
        bias = en_b; wh = en_w; b2 = en_b2; out = o_energy;
    } else {
        pred = 0; r0 = (long)(bid - 2 * N_PIT_TILES) * 64;
        bias = dur_b; wh = dur_w; b2 = dur_b2; out = o_logdur;
    }
    // B uint4 base for this pred/warpN/lane
    const uint4* Bbase = g_wblob + ((size_t)pred * 4 * 16 * 16 + warpN * 4) * 32 + lane;

    // bias + head weights + headsum init
    for (int i = tid; i < NLc * Hc; i += 256) bias_s[i] = bias[i];
    whead_s[tid] = wh[tid];
    if (tid < 64) headsum[tid] = 0.f;

    // A init: fp32 input -> fp16 in SMEM (gather for pitch/energy)
    // tids 0-127 write rows 0-31 (half 0), tids 128-255 rows 32-63 (half 1)
    {
        const int row = tid >> 2;
        const int c0  = (tid & 3) * 64;
        const long r  = r0 + row;
        const float* xr;
        bool zero = false;
        if (pred == 0) {
            xr = x + r * (long)Hc + c0;
        } else {
            const long b = r / Lc;
            xr = x + ((long)b * Tc + g_idx[r]) * (long)Hc + c0;
            zero = (g_mmask[r] != 0);
        }
        __half* dh = h_hi + row * PITCH + c0;
        #pragma unroll
        for (int q = 0; q < 16; q++) {
            float4 v = ((const float4*)xr)[q];
            if (zero) v = make_float4(0.f, 0.f, 0.f, 0.f);
            *(uint32_t*)(dh + q * 4)     = pack_h2(v.x, v.y);
            *(uint32_t*)(dh + q * 4 + 2) = pack_h2(v.z, v.w);
        }
    }
    // one FULL sync: bias/whead (written block-wide) + own-half A visible
    __syncthreads();

    // per-warp ldmatrix base addresses (bytes), one per m-subtile
    const uint32_t hbase = smem_u32(h_hi);
    uint32_t a_addr[2];
    #pragma unroll
    for (int m = 0; m < 2; m++) {
        const int rr = warpM * 32 + m * 16 + (lane & 15);
        a_addr[m] = hbase + (uint32_t)(rr * PITCH + (lane >> 4) * 8) * 2;
    }

    float acc[2][8][4];
    #pragma unroll
    for (int m = 0; m < 2; m++)
        #pragma unroll
        for (int j = 0; j < 8; j++)
            #pragma unroll
            for (int q = 0; q < 4; q++) acc[m][j][q] = 0.f;

    float hp[4] = {0.f, 0.f, 0.f, 0.f};   // head partials

    #pragma unroll 1
    for (int l = 0; l < NLc; l++) {
        const uint4* Bl = Bbase + (size_t)l * 16 * 16 * 32;   // layer base

        uint4 B0[4], B1[4];
        #pragma unroll
        for (int jj = 0; jj < 4; jj++) B0[jj] = __ldg(Bl + jj * 32);

        // 2x-unrolled kstep loop: even kstep uses B0 (prefetches B1),
        // odd kstep uses B1 (prefetches B0). No register rotation.
        #pragma unroll 1
        for (int ks2 = 0; ks2 < 8; ks2++) {
            {   // even kstep: 2*ks2
                const int ks = 2 * ks2;
                uint32_t a[2][4];
                ldmatrix_x4(a[0], a_addr[0] + ks * 32);
                ldmatrix_x4(a[1], a_addr[1] + ks * 32);
                const uint4* Bk = Bl + (size_t)(ks + 1) * 16 * 32;
                #pragma unroll
                for (int jj = 0; jj < 4; jj++) B1[jj] = __ldg(Bk + jj * 32);
                #pragma unroll
                for (int jj = 0; jj < 4; jj++) {
                    mma16816(acc[0][2 * jj],     a[0], B0[jj].x, B0[jj].y);
                    mma16816(acc[1][2 * jj],     a[1], B0[jj].x, B0[jj].y);
                    mma16816(acc[0][2 * jj + 1], a[0], B0[jj].z, B0[jj].w);
                    mma16816(acc[1][2 * jj + 1], a[1], B0[jj].z, B0[jj].w);
                }
            }
            {   // odd kstep: 2*ks2+1
                const int ks = 2 * ks2 + 1;
                uint32_t a[2][4];
                ldmatrix_x4(a[0], a_addr[0] + ks * 32);
                ldmatrix_x4(a[1], a_addr[1] + ks * 32);
                if (ks2 < 7) {
                    const uint4* Bk = Bl + (size_t)(ks + 1) * 16 * 32;
                    #pragma unroll
                    for (int jj = 0; jj < 4; jj++) B0[jj] = __ldg(Bk + jj * 32);
                }
                #pragma unroll
                for (int jj = 0; jj < 4; jj++) {
                    mma16816(acc[0][2 * jj],     a[0], B1[jj].x, B1[jj].y);
                    mma16816(acc[1][2 * jj],     a[1], B1[jj].x, B1[jj].y);
                    mma16816(acc[0][2 * jj + 1], a[0], B1[jj].z, B1[jj].w);
                    mma16816(acc[1][2 * jj + 1], a[1], B1[jj].z, B1[jj].w);
                }
            }
        }

        // ---- layer epilogue (independent per half: named barriers) ----
        const float* bl = bias_s + l * Hc;
        if (l < NLc - 1) {
            half_bar(barid);   // this half's 4 warps done reading A rows
            #pragma unroll
            for (int m = 0; m < 2; m++) {
                const int rr = warpM * 32 + m * 16 + g;
                #pragma unroll
                for (int j = 0; j < 8; j++) {
                    const int col = warpN * 64 + j * 8 + tg * 2;
                    float v0 = fmaxf(acc[m][j][0] + bl[col],     0.f);
                    float v1 = fmaxf(acc[m][j][1] + bl[col + 1], 0.f);
                    float v2 = fmaxf(acc[m][j][2] + bl[col],     0.f);
                    float v3 = fmaxf(acc[m][j][3] + bl[col + 1], 0.f);
                    *(uint32_t*)(h_hi + rr * PITCH + col)       = pack_h2(v0, v1);
                    *(uint32_t*)(h_hi + (rr + 8) * PITCH + col) = pack_h2(v2, v3);
                    acc[m][j][0] = 0.f; acc[m][j][1] = 0.f;
                    acc[m][j][2] = 0.f; acc[m][j][3] = 0.f;
                }
            }
            half_bar(barid);   // this half's new A visible to its 4 warps
        } else {
            #pragma unroll
            for (int m = 0; m < 2; m++) {
                #pragma unroll
                for (int j = 0; j < 8; j++) {
                    const int col = warpN * 64 + j * 8 + tg * 2;
                    float w0 = whead_s[col], w1 = whead_s[col + 1];
                    hp[m * 2]     += fmaxf(acc[m][j][0] + bl[col],     0.f) * w0
                                   + fmaxf(acc[m][j][1] + bl[col + 1], 0.f) * w1;
                    hp[m * 2 + 1] += fmaxf(acc[m][j][2] + bl[col],     0.f) * w0
                                   + fmaxf(acc[m][j][3] + bl[col + 1], 0.f) * w1;
                }
            }
        }
    }

    // head reduction: atomicAdd into per-row shared slots
    #pragma unroll
    for (int m = 0; m < 2; m++) {
        const int rr = warpM * 32 + m * 16 + g;
        atomicAdd(&headsum[rr],     hp[m * 2]);
        atomicAdd(&headsum[rr + 8], hp[m * 2 + 1]);
    }
    __syncthreads();   // FULL sync before cross-half headsum read

    if (tid < 64) {
        const long r = r0 + tid;
        float val = headsum[tid] + b2[0];
        const bool msk = (pred == 0) ? (src_mask[r] != 0) : (g_mmask[r] != 0);
        if (msk) val = 0.f;
        float res;
        if (pred == 0)      res = (tanhf(val) + 1.f) * src_seq[r * 3 + 2];
        else if (pred == 1) res = fmaxf(val, 0.f);
        else                res = val;
        out[r] = res;
    }

    // pitch CTAs also produce o_main = gather(x) + pemb + eemb for their rows
    if (pred == 1) {
        const int row = tid >> 2;
        const int c0  = (tid & 3) * 64;
        const long r  = r0 + row;
        const long b  = r / Lc;
        const float* xr = x + ((long)b * Tc + g_idx[r]) * (long)Hc + c0;
        const bool zero = (g_mmask[r] != 0);
        const int pi = (int)ceilf(pitch_t[r] * 256.0f);
        const int ei = (int)ceilf(energy_t[r] * 256.0f);
        const float4* pe = (const float4*)(pemb + (size_t)pi * Hc + c0);
        const float4* ee = (const float4*)(eemb + (size_t)ei * Hc + c0);
        float4* dst = (float4*)(o_main + r * (long)Hc + c0);
        #pragma unroll
        for (int q = 0; q < 16; q++) {
            float4 a = ((const float4*)xr)[q];
            if (zero) a = make_float4(0.f, 0.f, 0.f, 0.f);
            float4 p = pe[q], e = ee[q];
            float4 tmp;
            tmp.x = a.x + p.x + e.x;
            tmp.y = a.y + p.y + e.y;
            tmp.z = a.z + p.z + e.z;
            tmp.w = a.w + p.w + e.w;
            dst[q] = tmp;
        }
    }
}

// ============================================================
extern "C" void kernel_launch(void* const* d_in, const int* in_sizes, int n_in,
                              void* d_out, int out_size)
{
    const float* x        = (const float*)d_in[0];   // [B,T,H]
    const float* src_seq  = (const float*)d_in[1];   // [B,T,3]
    const int*   dur_t    = (const int*)  d_in[2];   // [B,T]
    const float* pitch_t  = (const float*)d_in[3];   // [B,L]
    const float* energy_t = (const float*)d_in[4];   // [B,L]
    const unsigned char* src_mask = (const unsigned char*)d_in[5]; // [B,T] bool

    const int base = n_in - 14;
    const float* dur_W  = (const float*)d_in[base + 0];
    const float* dur_b  = (const float*)d_in[base + 1];
    const float* dur_w  = (const float*)d_in[base + 2];
    const float* dur_b2 = (const float*)d_in[base + 3];
    const float* pit_W  = (const float*)d_in[base + 4];
    const float* pit_b  = (const float*)d_in[base + 5];
    const float* pit_w  = (const float*)d_in[base + 6];
    const float* pit_b2 = (const float*)d_in[base + 7];
    const float* en_W   = (const float*)d_in[base + 8];
    const float* en_b   = (const float*)d_in[base + 9];
    const float* en_w   = (const float*)d_in[base + 10];
    const float* en_b2  = (const float*)d_in[base + 11];
    const float* pemb   = (const float*)d_in[base + 12];
    const float* eemb   = (const float*)d_in[base + 13];

    float* out       = (float*)d_out;
    float* o_main    = out;                               // B*L*H
    float* o_logdur  = o_main + (size_t)ROWS_MEL * Hc;    // B*T
    float* o_pitch   = o_logdur + ROWS_DUR;               // B*L
    float* o_energy  = o_pitch + ROWS_MEL;                // B*L
    float* o_mellen  = o_energy + ROWS_MEL;               // B
    float* o_mmask   = o_mellen + Bc;                     // B*L

    cudaFuncSetAttribute(predictor_mma, cudaFuncAttributeMaxDynamicSharedMemorySize, SMEM_TOTAL);

    // 0) build fragment-order fp16 weight blob
    prep_kernel<<<768, 256>>>(dur_W, pit_W, en_W);

    // 1) length regulator metadata
    regulate_kernel<<<Bc, Tc>>>(dur_t, o_mellen, o_mmask);

    // 2) predictors + main output in one kernel
    predictor_mma<<<2 * N_PIT_TILES + N_DUR_TILES, 256, SMEM_TOTAL>>>(
        x, src_seq, src_mask,
        dur_b, pit_b, en_b, dur_w, pit_w, en_w, dur_b2, pit_b2, en_b2,
        pitch_t, energy_t, pemb, eemb,
        o_logdur, o_pitch, o_energy, o_main);
}